// round 9
// baseline (speedup 1.0000x reference)
#include <cuda_runtime.h>

// ---------------------------------------------------------------------------
// BottleNeck MHSA: B=16, C=512, H=W=32 (N=1024), NH=8, DK=64
//   q/k/v = W{q,k,v} @ x   (per-pixel 1x1 conv == GEMM 512x512 x 512x1024)
//   scores = softmax((q.k + q.rel_h + q.rel_w) / 8)
//   out = Wo @ (scores @ v) + bo
// All fp32. Three kernels; flash-style attention (no NxN materialization).
// ---------------------------------------------------------------------------

#define Bsz 16
#define Cch 512
#define NPIX 1024
#define NHh 8
#define DKd 64
#define BH (Bsz*NHh)   // 128

// Scratch (static device globals; allocated at module load, allowed)
__device__ float g_q[BH * DKd * NPIX];   // (bh, dk, n)  K-major
__device__ float g_k[BH * DKd * NPIX];   // (bh, dk, n)  K-major
__device__ float g_v[BH * NPIX * DKd];   // (bh, n, dk)  key-major
__device__ float g_o[Bsz * Cch * NPIX];  // (b, c=nh*64+dk, n)

// ---------------------------------------------------------------------------
// Kernel 1: QKV projection.  Y[o][n] = sum_c W[o][c] * x[b][c][n]
// 64x64 output tile, K-tile 32, 256 threads, 4x4 per thread.
// Channel decomposition for q/k/v: o = dk*8 + nh  (dk outer, head inner).
// ---------------------------------------------------------------------------
__global__ __launch_bounds__(256) void qkv_proj_kernel(
    const float* __restrict__ x,
    const float* __restrict__ wq,
    const float* __restrict__ wk,
    const float* __restrict__ wv)
{
    const int nt = blockIdx.x;        // 0..15  (n tile)
    const int mt = blockIdx.y;        // 0..7   (o tile)
    const int z  = blockIdx.z;        // b*3 + wsel
    const int b = z / 3, wsel = z - 3 * b;
    const float* w = (wsel == 0) ? wq : (wsel == 1 ? wk : wv);

    const int o0 = mt * 64, n0 = nt * 64;
    const float* xb = x + (size_t)b * Cch * NPIX;

    __shared__ float As[64][33];      // [o_local][kk]  (+1 pad)
    __shared__ float Bs[32][64];      // [kk][n_local]

    const int tid = threadIdx.x;
    const int tx = tid & 15, ty = tid >> 4;

    float acc[4][4];
#pragma unroll
    for (int r = 0; r < 4; r++)
#pragma unroll
        for (int c = 0; c < 4; c++) acc[r][c] = 0.f;

#pragma unroll 1
    for (int kt = 0; kt < 16; kt++) {
        const int c0 = kt * 32;
        // A tile 64x32
#pragma unroll
        for (int i = 0; i < 8; i++) {
            int idx = tid + i * 256;
            int row = idx >> 5, col = idx & 31;
            As[row][col] = w[(o0 + row) * Cch + c0 + col];
        }
        // B tile 32x64 (float4)
#pragma unroll
        for (int i = 0; i < 2; i++) {
            int idx = tid + i * 256;
            int kk = idx >> 4, n4 = (idx & 15) * 4;
            *(float4*)&Bs[kk][n4] = *(const float4*)&xb[(c0 + kk) * NPIX + n0 + n4];
        }
        __syncthreads();

#pragma unroll 8
        for (int kk = 0; kk < 32; kk++) {
            float af[4];
#pragma unroll
            for (int r = 0; r < 4; r++) af[r] = As[ty * 4 + r][kk];
            float4 b4 = *(float4*)&Bs[kk][tx * 4];
            float bf[4] = {b4.x, b4.y, b4.z, b4.w};
#pragma unroll
            for (int r = 0; r < 4; r++)
#pragma unroll
                for (int c = 0; c < 4; c++) acc[r][c] += af[r] * bf[c];
        }
        __syncthreads();
    }

    // Scatter epilogue
#pragma unroll
    for (int r = 0; r < 4; r++) {
        int o = o0 + ty * 4 + r;
        int nh = o & 7, dk = o >> 3;
        int bh = b * 8 + nh;
        if (wsel == 2) {
            // g_v: (bh, n, dk)
            size_t base = ((size_t)bh * NPIX + n0 + tx * 4) * DKd + dk;
#pragma unroll
            for (int c = 0; c < 4; c++) g_v[base + (size_t)c * DKd] = acc[r][c];
        } else {
            // g_q / g_k: (bh, dk, n)
            float* dst = (wsel == 0) ? g_q : g_k;
            float4 v4 = make_float4(acc[r][0], acc[r][1], acc[r][2], acc[r][3]);
            *(float4*)&dst[((size_t)bh * DKd + dk) * NPIX + n0 + tx * 4] = v4;
        }
    }
}

// ---------------------------------------------------------------------------
// Kernel 2: flash attention per (bh, q-tile of 64). 256 threads (16x16 map).
// Dynamic smem: Qs[64][64] (dk-major), Ks[64][64] (dk-major), Vs[64][64]
// (key-major), Ps[64][64] (q-major), RH[64][65] (bias table).
// ---------------------------------------------------------------------------
#define FLASH_SMEM_FLOATS (4 * 64 * 64 + 64 * 65)
#define FLASH_SMEM_BYTES  (FLASH_SMEM_FLOATS * 4)

__global__ __launch_bounds__(256) void flash_attn_kernel(
    const float* __restrict__ rel_h,
    const float* __restrict__ rel_w)
{
    extern __shared__ float sm[];
    float (*Qs)[64] = (float(*)[64])(sm);                 // [dk][p]
    float (*Ks)[64] = (float(*)[64])(sm + 64 * 64);       // [dk][key]
    float (*Vs)[64] = (float(*)[64])(sm + 2 * 64 * 64);   // [key][dk]
    float (*Ps)[64] = (float(*)[64])(sm + 3 * 64 * 64);   // [p][key]
    float (*RH)[65] = (float(*)[65])(sm + 4 * 64 * 64);   // [p][0..31]=rh, [p][32..63]=rw

    const int qt = blockIdx.x;        // 0..15
    const int bh = blockIdx.y;        // 0..127
    const int b = bh >> 3, nh = bh & 7;
    const int q0 = qt * 64;

    const int tid = threadIdx.x;
    const int tx = tid & 15, ty = tid >> 4;

    const float* qg = g_q + (size_t)bh * DKd * NPIX + q0;
    const float* kg = g_k + (size_t)bh * DKd * NPIX;
    const float* vg = g_v + (size_t)bh * NPIX * DKd;

    // Load Q tile (scaled by 1/sqrt(DK)=0.125 — scales both energy and bias)
#pragma unroll
    for (int i = 0; i < 4; i++) {
        int idx = tid + i * 256;                  // 1024 float4
        int dk = idx >> 4, c4 = (idx & 15) * 4;
        float4 t = *(const float4*)(qg + (size_t)dk * NPIX + c4);
        Qs[dk][c4 + 0] = t.x * 0.125f;
        Qs[dk][c4 + 1] = t.y * 0.125f;
        Qs[dk][c4 + 2] = t.z * 0.125f;
        Qs[dk][c4 + 3] = t.w * 0.125f;
    }
    __syncthreads();

    // Bias tables: RH[p][i]   = q[p] . rel_h[i - x_p + 31]   (i in 0..31)
    //              RH[p][32+j]= q[p] . rel_w[j - y_p + 31]   (j in 0..31)
    for (int e = tid; e < 4096; e += 256) {
        int p = e & 63, c = e >> 6;   // lanes share c -> rel row broadcast
        int pg = q0 + p;
        const float* rel;
        if (c < 32) { int xp = pg >> 5; rel = rel_h + (c - xp + 31) * DKd; }
        else        { int yp = pg & 31; rel = rel_w + ((c - 32) - yp + 31) * DKd; }
        float s = 0.f;
#pragma unroll 16
        for (int kk = 0; kk < 64; kk++) s += Qs[kk][p] * rel[kk];
        RH[p][c] = s;
    }
    __syncthreads();

    float m_[4], l_[4], oa[4][4];
#pragma unroll
    for (int r = 0; r < 4; r++) {
        m_[r] = -1e30f; l_[r] = 0.f;
#pragma unroll
        for (int c = 0; c < 4; c++) oa[r][c] = 0.f;
    }

#pragma unroll 1
    for (int kt = 0; kt < 16; kt++) {
        // Load K (direct, dk-major) and V (direct, key-major) tiles
#pragma unroll
        for (int i = 0; i < 4; i++) {
            int idx = tid + i * 256;
            int row = idx >> 4, c4 = (idx & 15) * 4;
            *(float4*)&Ks[row][c4] =
                *(const float4*)(kg + (size_t)row * NPIX + kt * 64 + c4);
            *(float4*)&Vs[row][c4] =
                *(const float4*)(vg + ((size_t)(kt * 64 + row)) * DKd + c4);
        }
        __syncthreads();

        // S = Q^T K  (both dk-major in smem)
        float s[4][4];
#pragma unroll
        for (int r = 0; r < 4; r++)
#pragma unroll
            for (int c = 0; c < 4; c++) s[r][c] = 0.f;
#pragma unroll 8
        for (int kk = 0; kk < 64; kk++) {
            float4 a4 = *(float4*)&Qs[kk][ty * 4];
            float4 b4 = *(float4*)&Ks[kk][tx * 4];
            float af[4] = {a4.x, a4.y, a4.z, a4.w};
            float bf[4] = {b4.x, b4.y, b4.z, b4.w};
#pragma unroll
            for (int r = 0; r < 4; r++)
#pragma unroll
                for (int c = 0; c < 4; c++) s[r][c] += af[r] * bf[c];
        }

        // Add relative-position bias (already scaled via Q)
#pragma unroll
        for (int c = 0; c < 4; c++) {
            int kglob = kt * 64 + tx * 4 + c;
            int i_ = kglob >> 5;      // Hk index (0..31)
            int j_ = kglob & 31;      // Wk index
#pragma unroll
            for (int r = 0; r < 4; r++) {
                int a = ty * 4 + r;
                s[r][c] += RH[a][i_] + RH[a][32 + j_];
            }
        }

        // Online softmax (row groups = 16 lanes within warp halves)
#pragma unroll
        for (int r = 0; r < 4; r++) {
            float tm = fmaxf(fmaxf(s[r][0], s[r][1]), fmaxf(s[r][2], s[r][3]));
#pragma unroll
            for (int o = 8; o >= 1; o >>= 1)
                tm = fmaxf(tm, __shfl_xor_sync(0xffffffffu, tm, o));
            float mnew = fmaxf(m_[r], tm);
            float sc = __expf(m_[r] - mnew);
            float rs = 0.f;
#pragma unroll
            for (int c = 0; c < 4; c++) { s[r][c] = __expf(s[r][c] - mnew); rs += s[r][c]; }
#pragma unroll
            for (int o = 8; o >= 1; o >>= 1)
                rs += __shfl_xor_sync(0xffffffffu, rs, o);
            l_[r] = l_[r] * sc + rs;
            m_[r] = mnew;
#pragma unroll
            for (int c = 0; c < 4; c++) oa[r][c] *= sc;
        }

        // Store P (q-major, conflict-free float4 rows)
#pragma unroll
        for (int r = 0; r < 4; r++) {
            float4 p4 = make_float4(s[r][0], s[r][1], s[r][2], s[r][3]);
            *(float4*)&Ps[ty * 4 + r][tx * 4] = p4;
        }
        __syncthreads();

        // O += P * V   (P read as scalar broadcast, V as float4)
#pragma unroll 8
        for (int kk = 0; kk < 64; kk++) {
            float pf[4];
#pragma unroll
            for (int r = 0; r < 4; r++) pf[r] = Ps[ty * 4 + r][kk];
            float4 v4 = *(float4*)&Vs[kk][tx * 4];
            float vf[4] = {v4.x, v4.y, v4.z, v4.w};
#pragma unroll
            for (int r = 0; r < 4; r++)
#pragma unroll
                for (int c = 0; c < 4; c++) oa[r][c] += pf[r] * vf[c];
        }
        __syncthreads();
    }

    // Epilogue: divide by row sums, write (b, c=nh*64+d, n) contiguous in n
    float il[4];
#pragma unroll
    for (int r = 0; r < 4; r++) il[r] = 1.f / l_[r];

    float* og = g_o + ((size_t)b * Cch + nh * DKd) * NPIX + q0;
#pragma unroll
    for (int c = 0; c < 4; c++) {
        int d = tx * 4 + c;
        float4 v4 = make_float4(oa[0][c] * il[0], oa[1][c] * il[1],
                                oa[2][c] * il[2], oa[3][c] * il[3]);
        *(float4*)&og[(size_t)d * NPIX + ty * 4] = v4;
    }
}

// ---------------------------------------------------------------------------
// Kernel 3: output projection.  out[b][o][n] = sum_c Wo[o][c]*g_o[b][c][n] + bo[o]
// ---------------------------------------------------------------------------
__global__ __launch_bounds__(256) void out_proj_kernel(
    const float* __restrict__ wo,
    const float* __restrict__ bo,
    float* __restrict__ out)
{
    const int nt = blockIdx.x;   // 0..15
    const int mt = blockIdx.y;   // 0..7
    const int b  = blockIdx.z;   // 0..15
    const int o0 = mt * 64, n0 = nt * 64;
    const float* xb = g_o + (size_t)b * Cch * NPIX;

    __shared__ float As[64][33];
    __shared__ float Bs[32][64];

    const int tid = threadIdx.x;
    const int tx = tid & 15, ty = tid >> 4;

    float acc[4][4];
#pragma unroll
    for (int r = 0; r < 4; r++)
#pragma unroll
        for (int c = 0; c < 4; c++) acc[r][c] = 0.f;

#pragma unroll 1
    for (int kt = 0; kt < 16; kt++) {
        const int c0 = kt * 32;
#pragma unroll
        for (int i = 0; i < 8; i++) {
            int idx = tid + i * 256;
            int row = idx >> 5, col = idx & 31;
            As[row][col] = wo[(o0 + row) * Cch + c0 + col];
        }
#pragma unroll
        for (int i = 0; i < 2; i++) {
            int idx = tid + i * 256;
            int kk = idx >> 4, n4 = (idx & 15) * 4;
            *(float4*)&Bs[kk][n4] = *(const float4*)&xb[(c0 + kk) * NPIX + n0 + n4];
        }
        __syncthreads();

#pragma unroll 8
        for (int kk = 0; kk < 32; kk++) {
            float af[4];
#pragma unroll
            for (int r = 0; r < 4; r++) af[r] = As[ty * 4 + r][kk];
            float4 b4 = *(float4*)&Bs[kk][tx * 4];
            float bf[4] = {b4.x, b4.y, b4.z, b4.w};
#pragma unroll
            for (int r = 0; r < 4; r++)
#pragma unroll
                for (int c = 0; c < 4; c++) acc[r][c] += af[r] * bf[c];
        }
        __syncthreads();
    }

#pragma unroll
    for (int r = 0; r < 4; r++) {
        int o = o0 + ty * 4 + r;
        float bb = bo[o];
        float4 v4 = make_float4(acc[r][0] + bb, acc[r][1] + bb,
                                acc[r][2] + bb, acc[r][3] + bb);
        *(float4*)&out[((size_t)b * Cch + o) * NPIX + n0 + tx * 4] = v4;
    }
}

// ---------------------------------------------------------------------------
// Launch
// ---------------------------------------------------------------------------
extern "C" void kernel_launch(void* const* d_in, const int* in_sizes, int n_in,
                              void* d_out, int out_size)
{
    (void)in_sizes; (void)n_in; (void)out_size;
    const float* x     = (const float*)d_in[0];
    const float* w_q   = (const float*)d_in[1];
    const float* w_k   = (const float*)d_in[2];
    const float* w_v   = (const float*)d_in[3];
    const float* w_o   = (const float*)d_in[4];
    const float* b_o   = (const float*)d_in[5];
    const float* rel_h = (const float*)d_in[6];
    const float* rel_w = (const float*)d_in[7];
    float* out = (float*)d_out;

    // Idempotent attribute set (not a stream op; safe under graph capture)
    cudaFuncSetAttribute(flash_attn_kernel,
                         cudaFuncAttributeMaxDynamicSharedMemorySize,
                         FLASH_SMEM_BYTES);

    qkv_proj_kernel<<<dim3(16, 8, 48), 256>>>(x, w_q, w_k, w_v);
    flash_attn_kernel<<<dim3(16, 128), 256, FLASH_SMEM_BYTES>>>(rel_h, rel_w);
    out_proj_kernel<<<dim3(16, 8, 16), 256>>>(w_o, b_o, out);
}

// round 10
// speedup vs baseline: 1.5605x; 1.5605x over previous
#include <cuda_runtime.h>

// ---------------------------------------------------------------------------
// BottleNeck MHSA: B=16, C=512, H=W=32 (N=1024), NH=8, DK=64.
// All fp32. 5 kernels: transpose_w, qkv(128x128x16 dbuf), transpose_v,
// flash(128q x 128k, 8x8 micro), out_proj.
// ---------------------------------------------------------------------------

#define Bsz 16
#define Cch 512
#define NPIX 1024
#define NHh 8
#define DKd 64
#define BH 128

__device__ float g_wt[4 * 512 * 512];        // transposed weights (c, o) x {q,k,v,o}
__device__ float g_q [BH * DKd * NPIX];      // (bh, dk, n)
__device__ float g_k [BH * DKd * NPIX];      // (bh, dk, n)
__device__ float g_vt[BH * DKd * NPIX];      // (bh, dk, n)  pre-transpose
__device__ float g_v [BH * NPIX * DKd];      // (bh, n, dk)
__device__ float g_o [Bsz * Cch * NPIX];     // (b, c=nh*64+d, n)

// ---------------------------------------------------------------------------
// Kernel 0: transpose the four 512x512 weight matrices into (c, o) layout.
// ---------------------------------------------------------------------------
__global__ __launch_bounds__(256) void transpose_w_kernel(
    const float* __restrict__ wq, const float* __restrict__ wk,
    const float* __restrict__ wv, const float* __restrict__ wo)
{
    __shared__ float t[32][33];
    const float* w = (blockIdx.z == 0) ? wq : (blockIdx.z == 1) ? wk
                   : (blockIdx.z == 2) ? wv : wo;
    float* wt = g_wt + (size_t)blockIdx.z * 512 * 512;
    const int c0 = blockIdx.x * 32, o0 = blockIdx.y * 32;
    const int tx = threadIdx.x & 31, ty = threadIdx.x >> 5;
#pragma unroll
    for (int i = 0; i < 4; i++)
        t[ty + i * 8][tx] = w[(o0 + ty + i * 8) * 512 + c0 + tx];
    __syncthreads();
#pragma unroll
    for (int i = 0; i < 4; i++)
        wt[(c0 + ty + i * 8) * 512 + o0 + tx] = t[tx][ty + i * 8];
}

// ---------------------------------------------------------------------------
// Kernel 1: QKV projection. 128x128 tile, K-tile 16, 256 thr, 8x8 microtile,
// double-buffered smem with register prefetch. All outputs dk-major.
// ---------------------------------------------------------------------------
__global__ __launch_bounds__(256, 2) void qkv_kernel(const float* __restrict__ x)
{
    const int nt = blockIdx.x, mt = blockIdx.y;
    const int z = blockIdx.z;
    const int b = z / 3, wsel = z - 3 * b;
    const int o0 = mt * 128, n0 = nt * 128;
    const float* wt = g_wt + (size_t)wsel * 512 * 512;
    const float* xb = x + (size_t)b * Cch * NPIX;

    __shared__ float As[2][16 * 128];
    __shared__ float Bs[2][16 * 128];

    const int tid = threadIdx.x;
    const int tx = tid & 15, ty = tid >> 4;

    float acc[8][8];
#pragma unroll
    for (int r = 0; r < 8; r++)
#pragma unroll
        for (int c = 0; c < 8; c++) acc[r][c] = 0.f;

    const int lkk0 = (tid + 0 * 256) >> 5, lc40 = ((tid + 0 * 256) & 31) * 4;
    const int lkk1 = (tid + 1 * 256) >> 5, lc41 = ((tid + 1 * 256) & 31) * 4;

    float4 pa0, pa1, pb0, pb1;
    // prefetch kt=0
    pa0 = *(const float4*)&wt[lkk0 * 512 + o0 + lc40];
    pa1 = *(const float4*)&wt[lkk1 * 512 + o0 + lc41];
    pb0 = *(const float4*)&xb[lkk0 * 1024 + n0 + lc40];
    pb1 = *(const float4*)&xb[lkk1 * 1024 + n0 + lc41];
    *(float4*)&As[0][lkk0 * 128 + lc40] = pa0;
    *(float4*)&As[0][lkk1 * 128 + lc41] = pa1;
    *(float4*)&Bs[0][lkk0 * 128 + lc40] = pb0;
    *(float4*)&Bs[0][lkk1 * 128 + lc41] = pb1;

#pragma unroll 1
    for (int kt = 0; kt < 32; kt++) {
        __syncthreads();
        const int cur = kt & 1;
        if (kt < 31) {
            const int c0 = (kt + 1) * 16;
            pa0 = *(const float4*)&wt[(c0 + lkk0) * 512 + o0 + lc40];
            pa1 = *(const float4*)&wt[(c0 + lkk1) * 512 + o0 + lc41];
            pb0 = *(const float4*)&xb[(c0 + lkk0) * 1024 + n0 + lc40];
            pb1 = *(const float4*)&xb[(c0 + lkk1) * 1024 + n0 + lc41];
        }
#pragma unroll 8
        for (int kk = 0; kk < 16; kk++) {
            float4 a0 = *(float4*)&As[cur][kk * 128 + ty * 4];
            float4 a1 = *(float4*)&As[cur][kk * 128 + 64 + ty * 4];
            float4 b0 = *(float4*)&Bs[cur][kk * 128 + tx * 4];
            float4 b1 = *(float4*)&Bs[cur][kk * 128 + 64 + tx * 4];
            float av[8] = {a0.x, a0.y, a0.z, a0.w, a1.x, a1.y, a1.z, a1.w};
            float bv[8] = {b0.x, b0.y, b0.z, b0.w, b1.x, b1.y, b1.z, b1.w};
#pragma unroll
            for (int r = 0; r < 8; r++)
#pragma unroll
                for (int c = 0; c < 8; c++) acc[r][c] += av[r] * bv[c];
        }
        if (kt < 31) {
            const int nxt = cur ^ 1;
            *(float4*)&As[nxt][lkk0 * 128 + lc40] = pa0;
            *(float4*)&As[nxt][lkk1 * 128 + lc41] = pa1;
            *(float4*)&Bs[nxt][lkk0 * 128 + lc40] = pb0;
            *(float4*)&Bs[nxt][lkk1 * 128 + lc41] = pb1;
        }
    }

    // Epilogue: o = dk*8 + nh decomposition; all dst layouts (bh, dk, n)
    float* dst = (wsel == 0) ? g_q : (wsel == 1) ? g_k : g_vt;
#pragma unroll
    for (int r = 0; r < 8; r++) {
        const int o = o0 + ((r < 4) ? (ty * 4 + r) : (64 + ty * 4 + r - 4));
        const int nh = o & 7, dk = o >> 3;
        const int bh = b * 8 + nh;
        float* p = dst + ((size_t)bh * 64 + dk) * 1024 + n0;
        *(float4*)&p[tx * 4]      = make_float4(acc[r][0], acc[r][1], acc[r][2], acc[r][3]);
        *(float4*)&p[64 + tx * 4] = make_float4(acc[r][4], acc[r][5], acc[r][6], acc[r][7]);
    }
}

// ---------------------------------------------------------------------------
// Kernel 2: transpose V (bh, dk, n) -> (bh, n, dk), coalesced both sides.
// ---------------------------------------------------------------------------
__global__ __launch_bounds__(256) void transpose_v_kernel()
{
    __shared__ float t[64][65];
    const int bh = blockIdx.y, n0 = blockIdx.x * 64;
    const float* src = g_vt + (size_t)bh * 64 * 1024;
    float* dst = g_v + (size_t)bh * 1024 * 64;
#pragma unroll
    for (int i = 0; i < 16; i++) {
        int id = threadIdx.x + i * 256;
        int d = id >> 6, n = id & 63;
        t[d][n] = src[d * 1024 + n0 + n];
    }
    __syncthreads();
#pragma unroll
    for (int i = 0; i < 16; i++) {
        int id = threadIdx.x + i * 256;
        int n = id >> 6, d = id & 63;
        dst[(size_t)(n0 + n) * 64 + d] = t[d][n];
    }
}

// ---------------------------------------------------------------------------
// Kernel 3: flash attention. Q-tile 128, K-tile 128, 256 thr, 8x8 S micro.
// ---------------------------------------------------------------------------
#define FL_QS 0
#define FL_KS (64 * 128)
#define FL_VS (2 * 64 * 128)
#define FL_PS (3 * 64 * 128)
#define FL_RB (3 * 64 * 128 + 128 * 132)
#define FL_TOT_FLOATS (3 * 64 * 128 + 128 * 132 + 128 * 68)
#define FL_SMEM_BYTES (FL_TOT_FLOATS * 4)

__global__ __launch_bounds__(256, 1) void flash_kernel(
    const float* __restrict__ rel_h, const float* __restrict__ rel_w)
{
    extern __shared__ float sm[];
    float* Qs = sm + FL_QS;   // [64][128] dk-major
    float* Ks = sm + FL_KS;   // [64][128] dk-major
    float* Vs = sm + FL_VS;   // [128][64] key-major
    float* Ps = sm + FL_PS;   // [128][132] q-major
    float* RB = sm + FL_RB;   // [128][68]: [0..31]=h-dots, [32..63]=w-dots

    const int qt = blockIdx.x;     // 0..7
    const int bh = blockIdx.y;     // 0..127
    const int b = bh >> 3, nh = bh & 7;
    const int q0 = qt * 128;
    const int tid = threadIdx.x, tx = tid & 15, ty = tid >> 4;

    const float* qg = g_q + (size_t)bh * 64 * 1024;
    const float* kg = g_k + (size_t)bh * 64 * 1024;
    const float* vg = g_v + (size_t)bh * 1024 * 64;

    // Q load, scaled by 1/sqrt(DK)=0.125 (scales energy AND bias)
#pragma unroll
    for (int i = 0; i < 8; i++) {
        int id = tid + i * 256;
        int dk = id >> 5, c4 = (id & 31) * 4;
        float4 t = *(const float4*)&qg[dk * 1024 + q0 + c4];
        t.x *= 0.125f; t.y *= 0.125f; t.z *= 0.125f; t.w *= 0.125f;
        *(float4*)&Qs[dk * 128 + c4] = t;
    }
    __syncthreads();

    // Bias tables: RB[p][i] = q_p . rel_h[i - xp + 31],
    //              RB[p][32+j] = q_p . rel_w[j - yp + 31]
    {
        const int p = tid & 127, half = tid >> 7;
        const int pg = q0 + p;
        float myq[64];
#pragma unroll
        for (int kk = 0; kk < 64; kk++) myq[kk] = Qs[kk * 128 + p];
        if (half == 0) {
            const int xp = pg >> 5;
            for (int c = 0; c < 32; c++) {
                const float* rr = rel_h + (c - xp + 31) * 64;
                float s = 0.f;
#pragma unroll
                for (int k4 = 0; k4 < 16; k4++) {
                    float4 r4 = *(const float4*)&rr[k4 * 4];
                    s += myq[k4 * 4 + 0] * r4.x + myq[k4 * 4 + 1] * r4.y
                       + myq[k4 * 4 + 2] * r4.z + myq[k4 * 4 + 3] * r4.w;
                }
                RB[p * 68 + c] = s;
            }
        } else {
            const int yp = pg & 31;
            for (int c = 0; c < 32; c++) {
                const float* rr = rel_w + (c - yp + 31) * 64;
                float s = 0.f;
#pragma unroll
                for (int k4 = 0; k4 < 16; k4++) {
                    float4 r4 = *(const float4*)&rr[k4 * 4];
                    s += myq[k4 * 4 + 0] * r4.x + myq[k4 * 4 + 1] * r4.y
                       + myq[k4 * 4 + 2] * r4.z + myq[k4 * 4 + 3] * r4.w;
                }
                RB[p * 68 + 32 + c] = s;
            }
        }
    }

    int rows[8];
#pragma unroll
    for (int r = 0; r < 8; r++)
        rows[r] = (r < 4) ? (ty * 4 + r) : (64 + ty * 4 + r - 4);

    float m_[8], l_[8], oa[8][4];
#pragma unroll
    for (int r = 0; r < 8; r++) {
        m_[r] = -1e30f; l_[r] = 0.f;
#pragma unroll
        for (int d = 0; d < 4; d++) oa[r][d] = 0.f;
    }

    const int j0 = (tx * 4) & 31;

#pragma unroll 1
    for (int kt = 0; kt < 8; kt++) {
        __syncthreads();
        // load K (dk-major) and V (key-major) tiles — coalesced float4
#pragma unroll
        for (int i = 0; i < 8; i++) {
            int id = tid + i * 256;
            int r_ = id >> 5, c4 = (id & 31) * 4;
            *(float4*)&Ks[r_ * 128 + c4] =
                *(const float4*)&kg[r_ * 1024 + kt * 128 + c4];
        }
#pragma unroll
        for (int i = 0; i < 8; i++) {
            int id = tid + i * 256;
            int r_ = id >> 4, c4 = (id & 15) * 4;
            *(float4*)&Vs[r_ * 64 + c4] =
                *(const float4*)&vg[(size_t)(kt * 128 + r_) * 64 + c4];
        }
        __syncthreads();

        // S = Q^T K, 8x8 per thread
        float s[8][8];
#pragma unroll
        for (int r = 0; r < 8; r++)
#pragma unroll
            for (int c = 0; c < 8; c++) s[r][c] = 0.f;
#pragma unroll 8
        for (int kk = 0; kk < 64; kk++) {
            float4 a0 = *(float4*)&Qs[kk * 128 + ty * 4];
            float4 a1 = *(float4*)&Qs[kk * 128 + 64 + ty * 4];
            float4 b0 = *(float4*)&Ks[kk * 128 + tx * 4];
            float4 b1 = *(float4*)&Ks[kk * 128 + 64 + tx * 4];
            float av[8] = {a0.x, a0.y, a0.z, a0.w, a1.x, a1.y, a1.z, a1.w};
            float bv[8] = {b0.x, b0.y, b0.z, b0.w, b1.x, b1.y, b1.z, b1.w};
#pragma unroll
            for (int r = 0; r < 8; r++)
#pragma unroll
                for (int c = 0; c < 8; c++) s[r][c] += av[r] * bv[c];
        }

        // bias add: keys c<4 -> klocal=tx*4+c, c>=4 -> 64+tx*4+(c-4)
        const int iA = kt * 4 + (tx >> 3);
        const int iB = kt * 4 + 2 + (tx >> 3);
#pragma unroll
        for (int r = 0; r < 8; r++) {
            const int row = rows[r];
            float hA = RB[row * 68 + iA];
            float hB = RB[row * 68 + iB];
            float4 w4 = *(float4*)&RB[row * 68 + 32 + j0];
            float wv[4] = {w4.x, w4.y, w4.z, w4.w};
#pragma unroll
            for (int c = 0; c < 4; c++) s[r][c]     += hA + wv[c];
#pragma unroll
            for (int c = 0; c < 4; c++) s[r][4 + c] += hB + wv[c];
        }

        // online softmax over 128 keys (8 local + 16-lane shuffle groups)
#pragma unroll
        for (int r = 0; r < 8; r++) {
            float tm = s[r][0];
#pragma unroll
            for (int c = 1; c < 8; c++) tm = fmaxf(tm, s[r][c]);
#pragma unroll
            for (int o = 8; o >= 1; o >>= 1)
                tm = fmaxf(tm, __shfl_xor_sync(0xffffffffu, tm, o));
            float mnew = fmaxf(m_[r], tm);
            float sc = __expf(m_[r] - mnew);
            float rs = 0.f;
#pragma unroll
            for (int c = 0; c < 8; c++) { s[r][c] = __expf(s[r][c] - mnew); rs += s[r][c]; }
#pragma unroll
            for (int o = 8; o >= 1; o >>= 1)
                rs += __shfl_xor_sync(0xffffffffu, rs, o);
            l_[r] = l_[r] * sc + rs;
            m_[r] = mnew;
#pragma unroll
            for (int d = 0; d < 4; d++) oa[r][d] *= sc;
        }

        // store P (q-major)
#pragma unroll
        for (int r = 0; r < 8; r++) {
            const int row = rows[r];
            *(float4*)&Ps[row * 132 + tx * 4] =
                make_float4(s[r][0], s[r][1], s[r][2], s[r][3]);
            *(float4*)&Ps[row * 132 + 64 + tx * 4] =
                make_float4(s[r][4], s[r][5], s[r][6], s[r][7]);
        }
        __syncthreads();

        // O += P @ V : 8q x 4d per thread, contraction over 128 keys, 4 at a time
#pragma unroll 4
        for (int c4 = 0; c4 < 32; c4++) {
            float4 vf0 = *(float4*)&Vs[(c4 * 4 + 0) * 64 + tx * 4];
            float4 vf1 = *(float4*)&Vs[(c4 * 4 + 1) * 64 + tx * 4];
            float4 vf2 = *(float4*)&Vs[(c4 * 4 + 2) * 64 + tx * 4];
            float4 vf3 = *(float4*)&Vs[(c4 * 4 + 3) * 64 + tx * 4];
#pragma unroll
            for (int r = 0; r < 8; r++) {
                float4 pf = *(float4*)&Ps[rows[r] * 132 + c4 * 4];
                oa[r][0] += pf.x * vf0.x + pf.y * vf1.x + pf.z * vf2.x + pf.w * vf3.x;
                oa[r][1] += pf.x * vf0.y + pf.y * vf1.y + pf.z * vf2.y + pf.w * vf3.y;
                oa[r][2] += pf.x * vf0.z + pf.y * vf1.z + pf.z * vf2.z + pf.w * vf3.z;
                oa[r][3] += pf.x * vf0.w + pf.y * vf1.w + pf.z * vf2.w + pf.w * vf3.w;
            }
        }
    }

    // epilogue: normalize, stage into RB[q][d] (RB no longer needed), write coalesced
#pragma unroll
    for (int r = 0; r < 8; r++) {
        float il = 1.f / l_[r];
        *(float4*)&RB[rows[r] * 68 + tx * 4] =
            make_float4(oa[r][0] * il, oa[r][1] * il, oa[r][2] * il, oa[r][3] * il);
    }
    __syncthreads();
    float* og = g_o + ((size_t)b * 512 + nh * 64) * 1024 + q0;
#pragma unroll
    for (int i = 0; i < 32; i++) {
        int id = tid + i * 256;
        int q = id & 127, d = id >> 7;
        og[d * 1024 + q] = RB[q * 68 + d];
    }
}

// ---------------------------------------------------------------------------
// Kernel 4: output projection (same GEMM structure) + bias, direct write.
// ---------------------------------------------------------------------------
__global__ __launch_bounds__(256, 2) void out_proj_kernel(
    const float* __restrict__ bo, float* __restrict__ out)
{
    const int nt = blockIdx.x, mt = blockIdx.y, b = blockIdx.z;
    const int o0 = mt * 128, n0 = nt * 128;
    const float* wt = g_wt + (size_t)3 * 512 * 512;
    const float* xb = g_o + (size_t)b * Cch * NPIX;

    __shared__ float As[2][16 * 128];
    __shared__ float Bs[2][16 * 128];

    const int tid = threadIdx.x;
    const int tx = tid & 15, ty = tid >> 4;

    float acc[8][8];
#pragma unroll
    for (int r = 0; r < 8; r++)
#pragma unroll
        for (int c = 0; c < 8; c++) acc[r][c] = 0.f;

    const int lkk0 = (tid + 0 * 256) >> 5, lc40 = ((tid + 0 * 256) & 31) * 4;
    const int lkk1 = (tid + 1 * 256) >> 5, lc41 = ((tid + 1 * 256) & 31) * 4;

    float4 pa0, pa1, pb0, pb1;
    pa0 = *(const float4*)&wt[lkk0 * 512 + o0 + lc40];
    pa1 = *(const float4*)&wt[lkk1 * 512 + o0 + lc41];
    pb0 = *(const float4*)&xb[lkk0 * 1024 + n0 + lc40];
    pb1 = *(const float4*)&xb[lkk1 * 1024 + n0 + lc41];
    *(float4*)&As[0][lkk0 * 128 + lc40] = pa0;
    *(float4*)&As[0][lkk1 * 128 + lc41] = pa1;
    *(float4*)&Bs[0][lkk0 * 128 + lc40] = pb0;
    *(float4*)&Bs[0][lkk1 * 128 + lc41] = pb1;

#pragma unroll 1
    for (int kt = 0; kt < 32; kt++) {
        __syncthreads();
        const int cur = kt & 1;
        if (kt < 31) {
            const int c0 = (kt + 1) * 16;
            pa0 = *(const float4*)&wt[(c0 + lkk0) * 512 + o0 + lc40];
            pa1 = *(const float4*)&wt[(c0 + lkk1) * 512 + o0 + lc41];
            pb0 = *(const float4*)&xb[(c0 + lkk0) * 1024 + n0 + lc40];
            pb1 = *(const float4*)&xb[(c0 + lkk1) * 1024 + n0 + lc41];
        }
#pragma unroll 8
        for (int kk = 0; kk < 16; kk++) {
            float4 a0 = *(float4*)&As[cur][kk * 128 + ty * 4];
            float4 a1 = *(float4*)&As[cur][kk * 128 + 64 + ty * 4];
            float4 b0 = *(float4*)&Bs[cur][kk * 128 + tx * 4];
            float4 b1 = *(float4*)&Bs[cur][kk * 128 + 64 + tx * 4];
            float av[8] = {a0.x, a0.y, a0.z, a0.w, a1.x, a1.y, a1.z, a1.w};
            float bv[8] = {b0.x, b0.y, b0.z, b0.w, b1.x, b1.y, b1.z, b1.w};
#pragma unroll
            for (int r = 0; r < 8; r++)
#pragma unroll
                for (int c = 0; c < 8; c++) acc[r][c] += av[r] * bv[c];
        }
        if (kt < 31) {
            const int nxt = cur ^ 1;
            *(float4*)&As[nxt][lkk0 * 128 + lc40] = pa0;
            *(float4*)&As[nxt][lkk1 * 128 + lc41] = pa1;
            *(float4*)&Bs[nxt][lkk0 * 128 + lc40] = pb0;
            *(float4*)&Bs[nxt][lkk1 * 128 + lc41] = pb1;
        }
    }

#pragma unroll
    for (int r = 0; r < 8; r++) {
        const int o = o0 + ((r < 4) ? (ty * 4 + r) : (64 + ty * 4 + r - 4));
        const float bb = bo[o];
        float* p = out + ((size_t)b * 512 + o) * 1024 + n0;
        *(float4*)&p[tx * 4] = make_float4(acc[r][0] + bb, acc[r][1] + bb,
                                           acc[r][2] + bb, acc[r][3] + bb);
        *(float4*)&p[64 + tx * 4] = make_float4(acc[r][4] + bb, acc[r][5] + bb,
                                                acc[r][6] + bb, acc[r][7] + bb);
    }
}

// ---------------------------------------------------------------------------
// Launch
// ---------------------------------------------------------------------------
extern "C" void kernel_launch(void* const* d_in, const int* in_sizes, int n_in,
                              void* d_out, int out_size)
{
    (void)in_sizes; (void)n_in; (void)out_size;
    const float* x     = (const float*)d_in[0];
    const float* w_q   = (const float*)d_in[1];
    const float* w_k   = (const float*)d_in[2];
    const float* w_v   = (const float*)d_in[3];
    const float* w_o   = (const float*)d_in[4];
    const float* b_o   = (const float*)d_in[5];
    const float* rel_h = (const float*)d_in[6];
    const float* rel_w = (const float*)d_in[7];
    float* out = (float*)d_out;

    cudaFuncSetAttribute(flash_kernel,
                         cudaFuncAttributeMaxDynamicSharedMemorySize,
                         FL_SMEM_BYTES);

    transpose_w_kernel<<<dim3(16, 16, 4), 256>>>(w_q, w_k, w_v, w_o);
    qkv_kernel<<<dim3(8, 4, 48), 256>>>(x);
    transpose_v_kernel<<<dim3(16, 128), 256>>>();
    flash_kernel<<<dim3(8, 128), 256, FL_SMEM_BYTES>>>(rel_h, rel_w);
    out_proj_kernel<<<dim3(8, 4, 16), 256>>>(b_o, out);
}